// round 3
// baseline (speedup 1.0000x reference)
#include <cuda_runtime.h>
#include <cuda_fp16.h>
#include <cstdint>

#define BB   8
#define NN   2048
#define FIN  256
#define DD   128
#define LEAK 0.2f

// Scratch (device globals — no allocation in kernel_launch)
__device__ __half g_Hh[BB * NN * DD];   // H_ in fp16, [16384, 128]
__device__ float  g_f1[BB * NN];
__device__ float  g_f2[BB * NN];

// ---------------------------------------------------------------------------
// Kernel 1: H_ = H @ W (fp32 tiled GEMM), write fp16 copy, fuse f1/f2 = H_ @ a1/a2
// Grid: 256 CTAs (64 rows each over 16384 flat rows), 256 threads.
// ---------------------------------------------------------------------------
__global__ __launch_bounds__(256) void proj_kernel(
    const float* __restrict__ H, const float* __restrict__ W,
    const float* __restrict__ a1, const float* __restrict__ a2)
{
    __shared__ float sHs[64][36];    // 64 rows x 32 k (padded)
    __shared__ float sWs[32][128];   // 32 k x 128 d

    const int tid = threadIdx.x;
    const int tx = tid & 31;         // col group (0..31) -> cols 4*tx..4*tx+3
    const int ty = tid >> 5;         // row group (0..7)  -> rows ty, ty+8, ..., ty+56
    const int row0 = blockIdx.x * 64;

    float acc[8][4];
#pragma unroll
    for (int r = 0; r < 8; r++)
#pragma unroll
        for (int c = 0; c < 4; c++) acc[r][c] = 0.f;

    for (int k0 = 0; k0 < FIN; k0 += 32) {
#pragma unroll
        for (int h = 0; h < 2; h++) {
            int r = (tid >> 3) + h * 32;                  // 0..63
            float4 v = *(const float4*)(H + (size_t)(row0 + r) * FIN + k0 + (tid & 7) * 4);
            *(float4*)&sHs[r][(tid & 7) * 4] = v;
        }
#pragma unroll
        for (int h = 0; h < 4; h++) {
            int k = (tid >> 5) + h * 8;                   // 0..31
            float4 v = *(const float4*)(W + (size_t)(k0 + k) * DD + (tid & 31) * 4);
            *(float4*)&sWs[k][(tid & 31) * 4] = v;
        }
        __syncthreads();
#pragma unroll
        for (int k = 0; k < 32; k++) {
            float4 bv = *(float4*)&sWs[k][tx * 4];
#pragma unroll
            for (int r = 0; r < 8; r++) {
                float a = sHs[ty + 8 * r][k];             // broadcast within warp
                acc[r][0] += a * bv.x;
                acc[r][1] += a * bv.y;
                acc[r][2] += a * bv.z;
                acc[r][3] += a * bv.w;
            }
        }
        __syncthreads();
    }

    const float4 a1v = *(const float4*)(a1 + tx * 4);
    const float4 a2v = *(const float4*)(a2 + tx * 4);

#pragma unroll
    for (int r = 0; r < 8; r++) {
        size_t g = (size_t)row0 + ty + 8 * r;
        // fp16 copy of H_
        __half2 h01 = __floats2half2_rn(acc[r][0], acc[r][1]);
        __half2 h23 = __floats2half2_rn(acc[r][2], acc[r][3]);
        uint2 pk;
        pk.x = *(uint32_t*)&h01;
        pk.y = *(uint32_t*)&h23;
        *(uint2*)(&g_Hh[g * DD + tx * 4]) = pk;
        // f1/f2 row dots (warp = fixed ty, lanes = tx -> full row covered)
        float p1 = acc[r][0] * a1v.x + acc[r][1] * a1v.y + acc[r][2] * a1v.z + acc[r][3] * a1v.w;
        float p2 = acc[r][0] * a2v.x + acc[r][1] * a2v.y + acc[r][2] * a2v.z + acc[r][3] * a2v.w;
#pragma unroll
        for (int off = 16; off; off >>= 1) {
            p1 += __shfl_xor_sync(0xffffffffu, p1, off);
            p2 += __shfl_xor_sync(0xffffffffu, p2, off);
        }
        if (tx == 0) {
            g_f1[g] = p1;
            g_f2[g] = p2;
        }
    }
}

// ---------------------------------------------------------------------------
// ldmatrix / mma helpers
// ---------------------------------------------------------------------------
__device__ __forceinline__ void ldm_x4(uint32_t& r0, uint32_t& r1, uint32_t& r2, uint32_t& r3,
                                       uint32_t addr)
{
    asm volatile("ldmatrix.sync.aligned.m8n8.x4.shared.b16 {%0,%1,%2,%3}, [%4];"
                 : "=r"(r0), "=r"(r1), "=r"(r2), "=r"(r3)
                 : "r"(addr));
}
__device__ __forceinline__ void ldm_x4_t(uint32_t& r0, uint32_t& r1, uint32_t& r2, uint32_t& r3,
                                         uint32_t addr)
{
    asm volatile("ldmatrix.sync.aligned.m8n8.x4.trans.shared.b16 {%0,%1,%2,%3}, [%4];"
                 : "=r"(r0), "=r"(r1), "=r"(r2), "=r"(r3)
                 : "r"(addr));
}
__device__ __forceinline__ void mma16816(float* c, uint32_t a0, uint32_t a1, uint32_t a2,
                                         uint32_t a3, uint32_t b0, uint32_t b1)
{
    asm volatile(
        "mma.sync.aligned.m16n8k16.row.col.f32.f16.f16.f32 "
        "{%0,%1,%2,%3}, {%4,%5,%6,%7}, {%8,%9}, {%0,%1,%2,%3};"
        : "+f"(c[0]), "+f"(c[1]), "+f"(c[2]), "+f"(c[3])
        : "r"(a0), "r"(a1), "r"(a2), "r"(a3), "r"(b0), "r"(b1));
}

// ---------------------------------------------------------------------------
// Kernel 2: fused attention. CTA = 32 i-rows of one batch; loop over 64-wide j
// tiles: p = (A>0)?exp(leaky(f1_i+f2_j)):1 -> smem (half), Z in fp32 regs,
// O += P @ H_half via mma.sync; epilogue divides by Z.
// Grid: (64 i-tiles, 8 batches) = 512 CTAs, 256 threads (8 warps).
// ---------------------------------------------------------------------------
__global__ __launch_bounds__(256) void gat_main_kernel(
    const float* __restrict__ A, float* __restrict__ out)
{
    __shared__ __half sP[32][72];    // P tile (32 x 64, pad 8) — stride 144B (36w ≡ 4 mod 32)
    __shared__ __half sH[64][136];   // H tile (64 x 128, pad 8) — stride 272B (68w ≡ 4 mod 32)
    __shared__ float  sZ[32];

    const int tid  = threadIdx.x;
    const int lane = tid & 31;
    const int w    = tid >> 5;
    const int b    = blockIdx.y;
    const int i0   = blockIdx.x * 32;

    const float* Ab = A + (size_t)b * NN * NN;

    // f1 for this warp's 4 rows (w*4 .. w*4+3)
    float rf1[4];
#pragma unroll
    for (int r = 0; r < 4; r++) rf1[r] = g_f1[b * NN + i0 + w * 4 + r];

    float zacc[4] = {0.f, 0.f, 0.f, 0.f};
    float acc[4][4];
#pragma unroll
    for (int nb = 0; nb < 4; nb++)
#pragma unroll
        for (int c = 0; c < 4; c++) acc[nb][c] = 0.f;

    const uint32_t spBase = (uint32_t)__cvta_generic_to_shared(&sP[0][0]);
    const uint32_t shBase = (uint32_t)__cvta_generic_to_shared(&sH[0][0]);

    const int mb = w & 1;    // m-block (0..1): rows mb*16..mb*16+15
    const int nq = w >> 1;   // n-quarter (0..3): cols nq*32..nq*32+31

    const uint32_t ldmRow  = (uint32_t)(lane & 15);
    const uint32_t ldmColO = (uint32_t)((lane >> 4) << 3);

    for (int j0 = 0; j0 < NN; j0 += 64) {
        // --- compute P tile (rows w*4..w*4+3, lane covers j = 2*lane, 2*lane+1) ---
        float2 f2v = *(const float2*)(&g_f2[b * NN + j0 + 2 * lane]);
#pragma unroll
        for (int r = 0; r < 4; r++) {
            int i = w * 4 + r;
            float2 av = *(const float2*)(Ab + (size_t)(i0 + i) * NN + j0 + 2 * lane);
            float s0 = rf1[r] + f2v.x;
            s0 = s0 > 0.f ? s0 : LEAK * s0;
            float p0 = (av.x > 0.f) ? __expf(s0) : 1.0f;
            float s1 = rf1[r] + f2v.y;
            s1 = s1 > 0.f ? s1 : LEAK * s1;
            float p1 = (av.y > 0.f) ? __expf(s1) : 1.0f;
            zacc[r] += p0 + p1;
            ((__half2*)&sP[i][0])[lane] = __floats2half2_rn(p0, p1);
        }
        // --- copy H_half tile [j0..j0+63][0..127] into smem ---
#pragma unroll
        for (int p = 0; p < 4; p++) {
            int idx = tid + p * 256;
            int row = idx >> 4;
            int c16 = idx & 15;
            uint4 v = *(const uint4*)(&g_Hh[(size_t)(b * NN + j0 + row) * DD + c16 * 8]);
            *(uint4*)(&sH[row][c16 * 8]) = v;
        }
        __syncthreads();

        // --- MMA: O(32x128) += P(32x64) @ H(64x128) ---
#pragma unroll
        for (int ks = 0; ks < 4; ks++) {
            uint32_t a0, a1, a2, a3;
            uint32_t aAddr = spBase +
                (((uint32_t)(mb * 16) + ldmRow) * 72u + (uint32_t)(ks * 16) + ldmColO) * 2u;
            ldm_x4(a0, a1, a2, a3, aAddr);
#pragma unroll
            for (int nbp = 0; nbp < 2; nbp++) {
                uint32_t b0, b1, b2, b3;
                uint32_t bAddr = shBase +
                    (((uint32_t)(ks * 16) + ldmRow) * 136u +
                     (uint32_t)(nq * 32 + nbp * 16) + ldmColO) * 2u;
                ldm_x4_t(b0, b1, b2, b3, bAddr);
                mma16816(acc[nbp * 2],     a0, a1, a2, a3, b0, b1);
                mma16816(acc[nbp * 2 + 1], a0, a1, a2, a3, b2, b3);
            }
        }
        __syncthreads();
    }

    // --- reduce Z per row, broadcast via smem ---
#pragma unroll
    for (int r = 0; r < 4; r++) {
        float z = zacc[r];
#pragma unroll
        for (int off = 16; off; off >>= 1) z += __shfl_xor_sync(0xffffffffu, z, off);
        if (lane == 0) sZ[w * 4 + r] = z;
    }
    __syncthreads();

    // --- epilogue: divide by Z, write out ---
    const int gid = lane >> 2;
    const int tig = lane & 3;
    const float inv0 = 1.f / sZ[mb * 16 + gid];
    const float inv1 = 1.f / sZ[mb * 16 + gid + 8];
    const size_t base0 = ((size_t)b * NN + i0 + mb * 16 + gid) * DD;
    const size_t base1 = base0 + (size_t)8 * DD;
#pragma unroll
    for (int nb = 0; nb < 4; nb++) {
        int col = nq * 32 + nb * 8 + tig * 2;
        out[base0 + col]     = acc[nb][0] * inv0;
        out[base0 + col + 1] = acc[nb][1] * inv0;
        out[base1 + col]     = acc[nb][2] * inv1;
        out[base1 + col + 1] = acc[nb][3] * inv1;
    }
}

// ---------------------------------------------------------------------------
extern "C" void kernel_launch(void* const* d_in, const int* in_sizes, int n_in,
                              void* d_out, int out_size)
{
    (void)in_sizes; (void)n_in; (void)out_size;
    const float* A  = (const float*)d_in[0];   // [8, 2048, 2048]
    const float* H  = (const float*)d_in[1];   // [8, 2048, 256]
    const float* W  = (const float*)d_in[2];   // [256, 128]
    const float* a1 = (const float*)d_in[3];   // [128, 1]
    const float* a2 = (const float*)d_in[4];   // [128, 1]
    float* out = (float*)d_out;                // [8, 2048, 128] fp32

    proj_kernel<<<(BB * NN) / 64, 256>>>(H, W, a1, a2);

    dim3 grid(NN / 32, BB);
    gat_main_kernel<<<grid, 256>>>(A, out);
}

// round 4
// speedup vs baseline: 1.2380x; 1.2380x over previous
#include <cuda_runtime.h>
#include <cuda_fp16.h>
#include <cstdint>

#define BB   8
#define NN   2048
#define FIN  256
#define DD   128
#define LEAK 0.2f

// Scratch (device globals — no allocation in kernel_launch)
__device__ __half g_Hh[BB * NN * DD];   // H_ in fp16, [16384, 128]
__device__ float  g_f1[BB * NN];
__device__ float  g_f2[BB * NN];

// ---------------------------------------------------------------------------
// Kernel 1: H_ = H @ W (fp32 tiled GEMM), write fp16 copy, fuse f1/f2 = H_ @ a1/a2
// ---------------------------------------------------------------------------
__global__ __launch_bounds__(256) void proj_kernel(
    const float* __restrict__ H, const float* __restrict__ W,
    const float* __restrict__ a1, const float* __restrict__ a2)
{
    __shared__ float sHs[64][36];
    __shared__ float sWs[32][128];

    const int tid = threadIdx.x;
    const int tx = tid & 31;
    const int ty = tid >> 5;
    const int row0 = blockIdx.x * 64;

    float acc[8][4];
#pragma unroll
    for (int r = 0; r < 8; r++)
#pragma unroll
        for (int c = 0; c < 4; c++) acc[r][c] = 0.f;

    for (int k0 = 0; k0 < FIN; k0 += 32) {
#pragma unroll
        for (int h = 0; h < 2; h++) {
            int r = (tid >> 3) + h * 32;
            float4 v = *(const float4*)(H + (size_t)(row0 + r) * FIN + k0 + (tid & 7) * 4);
            *(float4*)&sHs[r][(tid & 7) * 4] = v;
        }
#pragma unroll
        for (int h = 0; h < 4; h++) {
            int k = (tid >> 5) + h * 8;
            float4 v = *(const float4*)(W + (size_t)(k0 + k) * DD + (tid & 31) * 4);
            *(float4*)&sWs[k][(tid & 31) * 4] = v;
        }
        __syncthreads();
#pragma unroll
        for (int k = 0; k < 32; k++) {
            float4 bv = *(float4*)&sWs[k][tx * 4];
#pragma unroll
            for (int r = 0; r < 8; r++) {
                float a = sHs[ty + 8 * r][k];
                acc[r][0] += a * bv.x;
                acc[r][1] += a * bv.y;
                acc[r][2] += a * bv.z;
                acc[r][3] += a * bv.w;
            }
        }
        __syncthreads();
    }

    const float4 a1v = *(const float4*)(a1 + tx * 4);
    const float4 a2v = *(const float4*)(a2 + tx * 4);

#pragma unroll
    for (int r = 0; r < 8; r++) {
        size_t g = (size_t)row0 + ty + 8 * r;
        __half2 h01 = __floats2half2_rn(acc[r][0], acc[r][1]);
        __half2 h23 = __floats2half2_rn(acc[r][2], acc[r][3]);
        uint2 pk;
        pk.x = *(uint32_t*)&h01;
        pk.y = *(uint32_t*)&h23;
        *(uint2*)(&g_Hh[g * DD + tx * 4]) = pk;
        float p1 = acc[r][0] * a1v.x + acc[r][1] * a1v.y + acc[r][2] * a1v.z + acc[r][3] * a1v.w;
        float p2 = acc[r][0] * a2v.x + acc[r][1] * a2v.y + acc[r][2] * a2v.z + acc[r][3] * a2v.w;
#pragma unroll
        for (int off = 16; off; off >>= 1) {
            p1 += __shfl_xor_sync(0xffffffffu, p1, off);
            p2 += __shfl_xor_sync(0xffffffffu, p2, off);
        }
        if (tx == 0) {
            g_f1[g] = p1;
            g_f2[g] = p2;
        }
    }
}

// ---------------------------------------------------------------------------
// PTX helpers
// ---------------------------------------------------------------------------
__device__ __forceinline__ void cp_async16(uint32_t smem_addr, const void* gptr)
{
    asm volatile("cp.async.cg.shared.global [%0], [%1], 16;"
                 :: "r"(smem_addr), "l"(gptr));
}
__device__ __forceinline__ void cp_commit() { asm volatile("cp.async.commit_group;"); }
__device__ __forceinline__ void cp_wait1()  { asm volatile("cp.async.wait_group 1;"); }

__device__ __forceinline__ void ldm_x4(uint32_t& r0, uint32_t& r1, uint32_t& r2, uint32_t& r3,
                                       uint32_t addr)
{
    asm volatile("ldmatrix.sync.aligned.m8n8.x4.shared.b16 {%0,%1,%2,%3}, [%4];"
                 : "=r"(r0), "=r"(r1), "=r"(r2), "=r"(r3)
                 : "r"(addr));
}
__device__ __forceinline__ void ldm_x4_t(uint32_t& r0, uint32_t& r1, uint32_t& r2, uint32_t& r3,
                                         uint32_t addr)
{
    asm volatile("ldmatrix.sync.aligned.m8n8.x4.trans.shared.b16 {%0,%1,%2,%3}, [%4];"
                 : "=r"(r0), "=r"(r1), "=r"(r2), "=r"(r3)
                 : "r"(addr));
}
__device__ __forceinline__ void mma16816(float* c, uint32_t a0, uint32_t a1, uint32_t a2,
                                         uint32_t a3, uint32_t b0, uint32_t b1)
{
    asm volatile(
        "mma.sync.aligned.m16n8k16.row.col.f32.f16.f16.f32 "
        "{%0,%1,%2,%3}, {%4,%5,%6,%7}, {%8,%9}, {%0,%1,%2,%3};"
        : "+f"(c[0]), "+f"(c[1]), "+f"(c[2]), "+f"(c[3])
        : "r"(a0), "r"(a1), "r"(a2), "r"(a3), "r"(b0), "r"(b1));
}

// ---------------------------------------------------------------------------
// Kernel 2: fused attention, cp.async software pipeline.
//   A tiles : triple-buffered, issued 2 iterations ahead (DRAM stream)
//   H tiles : double-buffered, issued 1 iteration ahead (L2-resident)
//   sP      : single buffer (produced & consumed between the two barriers)
// Dynamic smem layout:
//   sA[3][32][64]  float  : 3 * 8192   = 24576 B
//   sH[2][64][136] half   : 2 * 17408  = 34816 B
//   sP[32][72]     half   :              4608 B
//   sZ[32]         float  :               128 B
// ---------------------------------------------------------------------------
#define T_TILES   (NN / 64)        // 32
#define SA_STRIDE 8192u            // bytes per A buffer
#define SH_STRIDE 17408u           // bytes per H buffer
#define OFF_SA    0u
#define OFF_SH    24576u
#define OFF_SP    (24576u + 34816u)          // 59392
#define OFF_SZ    (24576u + 34816u + 4608u)  // 64000
#define SMEM_MAIN (64000 + 128)              // 64128

__global__ __launch_bounds__(256, 3) void gat_main_kernel(
    const float* __restrict__ A, float* __restrict__ out)
{
    extern __shared__ char smem[];
    const uint32_t smBase = (uint32_t)__cvta_generic_to_shared(smem);
    const uint32_t saBase = smBase + OFF_SA;
    const uint32_t shBase = smBase + OFF_SH;
    const uint32_t spBase = smBase + OFF_SP;
    float* sZ = (float*)(smem + OFF_SZ);

    const int tid  = threadIdx.x;
    const int lane = tid & 31;
    const int w    = tid >> 5;
    const int b    = blockIdx.y;
    const int i0   = blockIdx.x * 32;

    const float*  Ab  = A + (size_t)b * NN * NN;
    const __half* Hhb = g_Hh + (size_t)b * NN * DD;

    // --- cp.async issue helpers (lambdas capture the fixed thread mapping) ---
    const int ldRow2 = tid >> 4;   // 0..15
    const int ldC16  = tid & 15;   // 0..15

    auto issueA = [&](int t) {
        if (t >= T_TILES) return;
        const uint32_t dbuf = saBase + (uint32_t)(t % 3) * SA_STRIDE;
        const int j0 = t * 64;
#pragma unroll
        for (int p = 0; p < 2; p++) {
            int row = ldRow2 + p * 16;                     // 0..31
            cp_async16(dbuf + (uint32_t)(row * 256 + ldC16 * 16),
                       Ab + (size_t)(i0 + row) * NN + j0 + ldC16 * 4);
        }
    };
    auto issueH = [&](int t) {
        if (t >= T_TILES) return;
        const uint32_t dbuf = shBase + (uint32_t)(t & 1) * SH_STRIDE;
        const int j0 = t * 64;
#pragma unroll
        for (int p = 0; p < 4; p++) {
            int row = ldRow2 + p * 16;                     // 0..63
            cp_async16(dbuf + (uint32_t)(row * 272 + ldC16 * 16),
                       Hhb + (size_t)(j0 + row) * DD + ldC16 * 8);
        }
    };

    // f1 for this warp's 4 rows
    float rf1[4];
#pragma unroll
    for (int r = 0; r < 4; r++) rf1[r] = g_f1[b * NN + i0 + w * 4 + r];

    float zacc[4] = {0.f, 0.f, 0.f, 0.f};
    float acc[4][4];
#pragma unroll
    for (int nb = 0; nb < 4; nb++)
#pragma unroll
        for (int c = 0; c < 4; c++) acc[nb][c] = 0.f;

    const int mb = w & 1;
    const int nq = w >> 1;
    const uint32_t ldmRow  = (uint32_t)(lane & 15);
    const uint32_t ldmColO = (uint32_t)((lane >> 4) << 3);

    // ---- prologue: groups {A0,H0}, {A1} ----
    issueA(0); issueH(0); cp_commit();
    issueA(1);            cp_commit();

    for (int t = 0; t < T_TILES; t++) {
        cp_wait1();            // A(t), H(t) landed (pending <= 1 group)
        __syncthreads();       // data visible; all warps done with mma(t-1)

        // issue ahead: H 1-ahead, A 2-ahead (each its own group)
        issueH(t + 1); cp_commit();
        issueA(t + 2); cp_commit();

        // --- exp phase: read A tile from smem, write P tile ---
        const float*  sAt = (const float*)(smem + OFF_SA + (uint32_t)(t % 3) * SA_STRIDE);
        const __half* dummy = nullptr; (void)dummy;
        float2 f2v = *(const float2*)(&g_f2[b * NN + t * 64 + 2 * lane]);
#pragma unroll
        for (int r = 0; r < 4; r++) {
            int i = w * 4 + r;
            float2 av = ((const float2*)(sAt + i * 64))[lane];
            float s0 = rf1[r] + f2v.x;
            s0 = s0 > 0.f ? s0 : LEAK * s0;
            float p0 = (av.x > 0.f) ? __expf(s0) : 1.0f;
            float s1 = rf1[r] + f2v.y;
            s1 = s1 > 0.f ? s1 : LEAK * s1;
            float p1 = (av.y > 0.f) ? __expf(s1) : 1.0f;
            zacc[r] += p0 + p1;
            __half2 ph = __floats2half2_rn(p0, p1);
            *(uint32_t*)(smem + OFF_SP + (uint32_t)(i * 144 + lane * 4)) = *(uint32_t*)&ph;
        }
        __syncthreads();       // sP visible to all warps

        // --- MMA: O(32x128) += P(32x64) @ H(64x128) ---
        const uint32_t shB = shBase + (uint32_t)(t & 1) * SH_STRIDE;
#pragma unroll
        for (int ks = 0; ks < 4; ks++) {
            uint32_t a0, a1, a2, a3;
            uint32_t aAddr = spBase +
                (((uint32_t)(mb * 16) + ldmRow) * 72u + (uint32_t)(ks * 16) + ldmColO) * 2u;
            ldm_x4(a0, a1, a2, a3, aAddr);
#pragma unroll
            for (int nbp = 0; nbp < 2; nbp++) {
                uint32_t b0, b1, b2, b3;
                uint32_t bAddr = shB +
                    (((uint32_t)(ks * 16) + ldmRow) * 136u +
                     (uint32_t)(nq * 32 + nbp * 16) + ldmColO) * 2u;
                ldm_x4_t(b0, b1, b2, b3, bAddr);
                mma16816(acc[nbp * 2],     a0, a1, a2, a3, b0, b1);
                mma16816(acc[nbp * 2 + 1], a0, a1, a2, a3, b2, b3);
            }
        }
        // no trailing barrier: top-of-loop barrier (next iter) orders reuse
    }

    // --- reduce Z per row, broadcast via smem ---
    __syncthreads();
#pragma unroll
    for (int r = 0; r < 4; r++) {
        float z = zacc[r];
#pragma unroll
        for (int off = 16; off; off >>= 1) z += __shfl_xor_sync(0xffffffffu, z, off);
        if (lane == 0) sZ[w * 4 + r] = z;
    }
    __syncthreads();

    // --- epilogue: divide by Z, write out ---
    const int gid = lane >> 2;
    const int tig = lane & 3;
    const float inv0 = 1.f / sZ[mb * 16 + gid];
    const float inv1 = 1.f / sZ[mb * 16 + gid + 8];
    const size_t base0 = ((size_t)b * NN + i0 + mb * 16 + gid) * DD;
    const size_t base1 = base0 + (size_t)8 * DD;
#pragma unroll
    for (int nb = 0; nb < 4; nb++) {
        int col = nq * 32 + nb * 8 + tig * 2;
        out[base0 + col]     = acc[nb][0] * inv0;
        out[base0 + col + 1] = acc[nb][1] * inv0;
        out[base1 + col]     = acc[nb][2] * inv1;
        out[base1 + col + 1] = acc[nb][3] * inv1;
    }
}

// ---------------------------------------------------------------------------
extern "C" void kernel_launch(void* const* d_in, const int* in_sizes, int n_in,
                              void* d_out, int out_size)
{
    (void)in_sizes; (void)n_in; (void)out_size;
    const float* A  = (const float*)d_in[0];   // [8, 2048, 2048]
    const float* H  = (const float*)d_in[1];   // [8, 2048, 256]
    const float* W  = (const float*)d_in[2];   // [256, 128]
    const float* a1 = (const float*)d_in[3];   // [128, 1]
    const float* a2 = (const float*)d_in[4];   // [128, 1]
    float* out = (float*)d_out;                // [8, 2048, 128] fp32

    proj_kernel<<<(BB * NN) / 64, 256>>>(H, W, a1, a2);

    cudaFuncSetAttribute(gat_main_kernel,
                         cudaFuncAttributeMaxDynamicSharedMemorySize, SMEM_MAIN);
    dim3 grid(NN / 32, BB);
    gat_main_kernel<<<grid, 256, SMEM_MAIN>>>(A, out);
}

// round 8
// speedup vs baseline: 1.8670x; 1.5081x over previous
#include <cuda_runtime.h>
#include <cuda_fp16.h>
#include <cstdint>

#define BB   8
#define NN   2048
#define FIN  256
#define DD   128
#define LEAK 0.2f

// Scratch (device globals — no allocation in kernel_launch)
__device__ __half g_Hh[BB * NN * DD];   // H_ in fp16, [16384, 128]
__device__ float  g_f1[BB * NN];
__device__ float  g_f2[BB * NN];

// ---------------------------------------------------------------------------
// Kernel 1: H_ = H @ W (fp32 tiled GEMM), write fp16 copy, fuse f1/f2 = H_ @ a1/a2
// ---------------------------------------------------------------------------
__global__ __launch_bounds__(256) void proj_kernel(
    const float* __restrict__ H, const float* __restrict__ W,
    const float* __restrict__ a1, const float* __restrict__ a2)
{
    __shared__ float sHs[64][36];
    __shared__ float sWs[32][128];

    const int tid = threadIdx.x;
    const int tx = tid & 31;
    const int ty = tid >> 5;
    const int row0 = blockIdx.x * 64;

    float acc[8][4];
#pragma unroll
    for (int r = 0; r < 8; r++)
#pragma unroll
        for (int c = 0; c < 4; c++) acc[r][c] = 0.f;

    for (int k0 = 0; k0 < FIN; k0 += 32) {
#pragma unroll
        for (int h = 0; h < 2; h++) {
            int r = (tid >> 3) + h * 32;
            float4 v = *(const float4*)(H + (size_t)(row0 + r) * FIN + k0 + (tid & 7) * 4);
            *(float4*)&sHs[r][(tid & 7) * 4] = v;
        }
#pragma unroll
        for (int h = 0; h < 4; h++) {
            int k = (tid >> 5) + h * 8;
            float4 v = *(const float4*)(W + (size_t)(k0 + k) * DD + (tid & 31) * 4);
            *(float4*)&sWs[k][(tid & 31) * 4] = v;
        }
        __syncthreads();
#pragma unroll
        for (int k = 0; k < 32; k++) {
            float4 bv = *(float4*)&sWs[k][tx * 4];
#pragma unroll
            for (int r = 0; r < 8; r++) {
                float a = sHs[ty + 8 * r][k];
                acc[r][0] += a * bv.x;
                acc[r][1] += a * bv.y;
                acc[r][2] += a * bv.z;
                acc[r][3] += a * bv.w;
            }
        }
        __syncthreads();
    }

    const float4 a1v = *(const float4*)(a1 + tx * 4);
    const float4 a2v = *(const float4*)(a2 + tx * 4);

#pragma unroll
    for (int r = 0; r < 8; r++) {
        size_t g = (size_t)row0 + ty + 8 * r;
        __half2 h01 = __floats2half2_rn(acc[r][0], acc[r][1]);
        __half2 h23 = __floats2half2_rn(acc[r][2], acc[r][3]);
        uint2 pk;
        pk.x = *(uint32_t*)&h01;
        pk.y = *(uint32_t*)&h23;
        *(uint2*)(&g_Hh[g * DD + tx * 4]) = pk;
        float p1 = acc[r][0] * a1v.x + acc[r][1] * a1v.y + acc[r][2] * a1v.z + acc[r][3] * a1v.w;
        float p2 = acc[r][0] * a2v.x + acc[r][1] * a2v.y + acc[r][2] * a2v.z + acc[r][3] * a2v.w;
#pragma unroll
        for (int off = 16; off; off >>= 1) {
            p1 += __shfl_xor_sync(0xffffffffu, p1, off);
            p2 += __shfl_xor_sync(0xffffffffu, p2, off);
        }
        if (tx == 0) {
            g_f1[g] = p1;
            g_f2[g] = p2;
        }
    }
}

// ---------------------------------------------------------------------------
// PTX helpers
// ---------------------------------------------------------------------------
__device__ __forceinline__ void cp_async16(uint32_t smem_addr, const void* gptr)
{
    asm volatile("cp.async.cg.shared.global [%0], [%1], 16;"
                 :: "r"(smem_addr), "l"(gptr));
}
__device__ __forceinline__ void cp_commit() { asm volatile("cp.async.commit_group;"); }
__device__ __forceinline__ void cp_wait1()  { asm volatile("cp.async.wait_group 1;"); }

__device__ __forceinline__ void ldm_x4(uint32_t& r0, uint32_t& r1, uint32_t& r2, uint32_t& r3,
                                       uint32_t addr)
{
    asm volatile("ldmatrix.sync.aligned.m8n8.x4.shared.b16 {%0,%1,%2,%3}, [%4];"
                 : "=r"(r0), "=r"(r1), "=r"(r2), "=r"(r3)
                 : "r"(addr));
}
__device__ __forceinline__ void ldm_x4_t(uint32_t& r0, uint32_t& r1, uint32_t& r2, uint32_t& r3,
                                         uint32_t addr)
{
    asm volatile("ldmatrix.sync.aligned.m8n8.x4.trans.shared.b16 {%0,%1,%2,%3}, [%4];"
                 : "=r"(r0), "=r"(r1), "=r"(r2), "=r"(r3)
                 : "r"(addr));
}
__device__ __forceinline__ void mma16816(float* c, uint32_t a0, uint32_t a1, uint32_t a2,
                                         uint32_t a3, uint32_t b0, uint32_t b1)
{
    asm volatile(
        "mma.sync.aligned.m16n8k16.row.col.f32.f16.f16.f32 "
        "{%0,%1,%2,%3}, {%4,%5,%6,%7}, {%8,%9}, {%0,%1,%2,%3};"
        : "+f"(c[0]), "+f"(c[1]), "+f"(c[2]), "+f"(c[3])
        : "r"(a0), "r"(a1), "r"(a2), "r"(a3), "r"(b0), "r"(b1));
}

// ---------------------------------------------------------------------------
// Kernel 2: fused attention, single-barrier pipelined loop.
//   CTA = 64 i-rows, 512 threads (16 warps: mb = w&3, nq = w>>2), 256 CTAs.
// Per iter t:
//   cp.async.wait_group 1 ; __syncwarp()
//       -> A(t) visible warp-wide (A rows are WARP-SELF-COPIED), H(t) landed
//   exp(t)  (A(t) smem -> P(t) in sP[t&1], fp32 Z accum)
//   issue {H(t+1)} , {A(t+2)}
//   __syncthreads()        -> publishes P(t) and every thread's waited H(t)
//   mma(P(t) @ H(t))
// Smem (all 16B-aligned strides; sH/sP use XOR-chunk swizzle, no pads):
//   sA[3][64][64]  f32 : 3*16384 = 49152
//   sH[3][64][128] f16 : 3*16384 = 49152   (ends 98304)
//   sP[2][64][64]  f16 : 2*8192  = 16384   (ends 114688)
//   sZ[64]         f32 :            256    -> total 114944 (x2 = 229888 <= 228KB)
// ---------------------------------------------------------------------------
#define T_TILES   (NN / 64)
#define SA_STRIDE 16384u
#define SH_STRIDE 16384u
#define SP_STRIDE 8192u
#define OFF_SA    0u
#define OFF_SH    49152u
#define OFF_SP    98304u
#define OFF_SZ    114688u
#define SMEM_MAIN 114944

__global__ __launch_bounds__(512, 2) void gat_main_kernel(
    const float* __restrict__ A, float* __restrict__ out)
{
    extern __shared__ char smem[];
    const uint32_t smBase = (uint32_t)__cvta_generic_to_shared(smem);
    const uint32_t saBase = smBase + OFF_SA;
    const uint32_t shBase = smBase + OFF_SH;
    const uint32_t spBase = smBase + OFF_SP;
    float* sZ = (float*)(smem + OFF_SZ);

    const int tid  = threadIdx.x;
    const int lane = tid & 31;
    const int w    = tid >> 5;          // 0..15
    const int b    = blockIdx.y;
    const int i0   = blockIdx.x * 64;

    const float*  Ab  = A + (size_t)b * NN * NN;
    const __half* Hhb = g_Hh + (size_t)b * NN * DD;

    // A(t): WARP-LOCAL copy — warp w copies exactly the 4 rows (4w..4w+3) that
    // it will read in the exp phase, so wait_group + __syncwarp suffices.
    // lane -> row = 4w + p*2 + (lane>>4), chunk = lane&15 (16B). Coalesced 256B.
    const int aRowSelf = 4 * w + (lane >> 4);
    const int aChunk   = lane & 15;
    auto issueA = [&](int t) {
        if (t >= T_TILES) return;
        const uint32_t dbuf = saBase + (uint32_t)(t % 3) * SA_STRIDE;
        const int j0 = t * 64;
#pragma unroll
        for (int p = 0; p < 2; p++) {
            int row = aRowSelf + p * 2;     // 4w .. 4w+3
            cp_async16(dbuf + (uint32_t)(row * 256 + aChunk * 16),
                       Ab + (size_t)(i0 + row) * NN + j0 + aChunk * 4);
        }
    };
    // H(t): 64x128 f16 tile, rows of 256B = 16 chunks, chunk ^= row&7 swizzle.
    // Consumed only after __syncthreads(), so the spread mapping is safe.
    const int ldRow = tid >> 4;         // 0..31
    const int ldC16 = tid & 15;         // 16B chunk index 0..15
    auto issueH = [&](int t) {
        if (t >= T_TILES) return;
        const uint32_t dbuf = shBase + (uint32_t)(t % 3) * SH_STRIDE;
        const int j0 = t * 64;
#pragma unroll
        for (int p = 0; p < 2; p++) {
            int row = ldRow + p * 32;   // 0..63
            int sw = ldC16 ^ (row & 7);
            cp_async16(dbuf + (uint32_t)(row * 256 + sw * 16),
                       Hhb + (size_t)(j0 + row) * DD + ldC16 * 8);
        }
    };

    // f1 for this warp's 4 exp-rows
    float rf1[4];
#pragma unroll
    for (int r = 0; r < 4; r++) rf1[r] = g_f1[b * NN + i0 + w * 4 + r];

    float zacc[4] = {0.f, 0.f, 0.f, 0.f};
    float acc[4][4];
#pragma unroll
    for (int nb = 0; nb < 4; nb++)
#pragma unroll
        for (int c = 0; c < 4; c++) acc[nb][c] = 0.f;

    const int mb = w & 3;               // m-block: rows mb*16 .. mb*16+15
    const int nq = w >> 2;              // n-quarter: cols nq*32 .. nq*32+31

    // ldmatrix per-lane addressing (precomputed swizzled offsets)
    const int aRow  = mb * 16 + (lane & 15);
    const int bRowL = lane & 15;
    const int hi    = lane >> 4;
    uint32_t aOff[4];
#pragma unroll
    for (int ks = 0; ks < 4; ks++)
        aOff[ks] = (uint32_t)(aRow * 128 + (((ks * 2 + hi) ^ (aRow & 7)) << 4));
    uint32_t bOff[4][2];
#pragma unroll
    for (int ks = 0; ks < 4; ks++) {
        int row = ks * 16 + bRowL;
#pragma unroll
        for (int nbp = 0; nbp < 2; nbp++)
            bOff[ks][nbp] = (uint32_t)(row * 256 + (((nq * 4 + nbp * 2 + hi) ^ (row & 7)) << 4));
    }
    const int pwChunk = lane >> 2;
    const int pwByte  = (lane & 3) * 4;

    // ---- prologue: G1={A0,H0}, G2={A1} ----
    issueA(0); issueH(0); cp_commit();
    issueA(1);            cp_commit();

    for (int t = 0; t < T_TILES; t++) {
        cp_wait1();            // this thread's A(t), H(t) copies complete
        __syncwarp();          // publish warp-self A(t) rows warp-wide

        // --- exp phase: A(t) smem -> P(t) in sP[t&1] ---
        const float* sAt = (const float*)(smem + OFF_SA + (uint32_t)(t % 3) * SA_STRIDE);
        const uint32_t spW = spBase + (uint32_t)(t & 1) * SP_STRIDE;
        float2 f2v = *(const float2*)(&g_f2[b * NN + t * 64 + 2 * lane]);
#pragma unroll
        for (int r = 0; r < 4; r++) {
            int i = w * 4 + r;
            float2 av = ((const float2*)(sAt + i * 64))[lane];
            float s0 = rf1[r] + f2v.x;
            s0 = fmaxf(s0, LEAK * s0);
            float p0 = (av.x > 0.f) ? __expf(s0) : 1.0f;
            float s1 = rf1[r] + f2v.y;
            s1 = fmaxf(s1, LEAK * s1);
            float p1 = (av.y > 0.f) ? __expf(s1) : 1.0f;
            zacc[r] += p0 + p1;
            __half2 ph = __floats2half2_rn(p0, p1);
            uint32_t addr = spW + (uint32_t)(i * 128 + ((pwChunk ^ (i & 7)) << 4) + pwByte);
            asm volatile("st.shared.b32 [%0], %1;" :: "r"(addr), "r"(*(uint32_t*)&ph));
        }

        // --- prefetch: {H(t+1)}, {A(t+2)} ---
        issueH(t + 1); cp_commit();
        issueA(t + 2); cp_commit();

        __syncthreads();   // P(t) + all threads' H(t) visible; rings safe

        // --- MMA: O(64x128) += P(t)(64x64) @ H(t)(64x128) ---
        const uint32_t spB = spBase + (uint32_t)(t & 1) * SP_STRIDE;
        const uint32_t shB = shBase + (uint32_t)(t % 3) * SH_STRIDE;
#pragma unroll
        for (int ks = 0; ks < 4; ks++) {
            uint32_t a0, a1, a2, a3;
            ldm_x4(a0, a1, a2, a3, spB + aOff[ks]);
#pragma unroll
            for (int nbp = 0; nbp < 2; nbp++) {
                uint32_t b0, b1, b2, b3;
                ldm_x4_t(b0, b1, b2, b3, shB + bOff[ks][nbp]);
                mma16816(acc[nbp * 2],     a0, a1, a2, a3, b0, b1);
                mma16816(acc[nbp * 2 + 1], a0, a1, a2, a3, b2, b3);
            }
        }
    }

    // --- reduce Z per row ---
#pragma unroll
    for (int r = 0; r < 4; r++) {
        float z = zacc[r];
#pragma unroll
        for (int off = 16; off; off >>= 1) z += __shfl_xor_sync(0xffffffffu, z, off);
        if (lane == 0) sZ[w * 4 + r] = z;
    }
    __syncthreads();

    // --- epilogue: divide by Z, write out (float2 stores) ---
    const int gid = lane >> 2;
    const int tig = lane & 3;
    const float inv0 = 1.f / sZ[mb * 16 + gid];
    const float inv1 = 1.f / sZ[mb * 16 + gid + 8];
    const size_t base0 = ((size_t)b * NN + i0 + mb * 16 + gid) * DD;
    const size_t base1 = base0 + (size_t)8 * DD;
#pragma unroll
    for (int nb = 0; nb < 4; nb++) {
        int col = nq * 32 + nb * 8 + tig * 2;
        float2 v0 = make_float2(acc[nb][0] * inv0, acc[nb][1] * inv0);
        float2 v1 = make_float2(acc[nb][2] * inv1, acc[nb][3] * inv1);
        *(float2*)(out + base0 + col) = v0;
        *(float2*)(out + base1 + col) = v1;
    }
}

// ---------------------------------------------------------------------------
extern "C" void kernel_launch(void* const* d_in, const int* in_sizes, int n_in,
                              void* d_out, int out_size)
{
    (void)in_sizes; (void)n_in; (void)out_size;
    const float* A  = (const float*)d_in[0];   // [8, 2048, 2048]
    const float* H  = (const float*)d_in[1];   // [8, 2048, 256]
    const float* W  = (const float*)d_in[2];   // [256, 128]
    const float* a1 = (const float*)d_in[3];   // [128, 1]
    const float* a2 = (const float*)d_in[4];   // [128, 1]
    float* out = (float*)d_out;                // [8, 2048, 128] fp32

    proj_kernel<<<(BB * NN) / 64, 256>>>(H, W, a1, a2);

    cudaFuncSetAttribute(gat_main_kernel,
                         cudaFuncAttributeMaxDynamicSharedMemorySize, SMEM_MAIN);
    dim3 grid(NN / 64, BB);
    gat_main_kernel<<<grid, 512, SMEM_MAIN>>>(A, out);
}